// round 14
// baseline (speedup 1.0000x reference)
#include <cuda_runtime.h>

// out[n, k=9*i+j, h, w] = sum_z A[n,z,h,w] * B[n,z, h+j-4, w+i-4]  (zero pad)
// N=8, Z=128, H=W=160.
//
// CTA tile TW=32 x TH=8. Threads (tx=4, h=8, j=9) = 288; warp == one j.
// Thread: 8 consecutive pixels, one row, 9 i-shifts. Accumulators are 36
// packed f32x2 pairs; inner product via fma.rn.f32x2 (rt=3 -> 1.33x fma
// throughput vs scalar FFMA, half the instructions). Only the 7 odd-offset
// b-pairs need explicit packs; even pairs alias float4 register halves.
// ZC=4 z-chunks, triple-buffered smem via cp.async.cg (zfill halo).

#define N_  8
#define Z_  128
#define H_  160
#define W_  160
#define TW  32
#define TH  8
#define ZC  4
#define NCH (Z_ / ZC)     // 32
#define AROW 36
#define BROW 44
#define BRN  16           // TH + 8
#define NT  288

#define ASZ (ZC * TH * AROW)      // floats per A buffer
#define BSZ (ZC * BRN * BROW)     // floats per B buffer

typedef unsigned long long u64;

__device__ __forceinline__ u64 pk(float lo, float hi) {
    u64 r;
    asm("mov.b64 %0, {%1, %2};" : "=l"(r) : "f"(lo), "f"(hi));
    return r;
}
__device__ __forceinline__ void fma2(u64& d, u64 a, u64 b) {
    asm("fma.rn.f32x2 %0, %1, %2, %0;" : "+l"(d) : "l"(a), "l"(b));
}
__device__ __forceinline__ float2 unpk(u64 v) {
    float lo, hi;
    asm("mov.b64 {%0, %1}, %2;" : "=f"(lo), "=f"(hi) : "l"(v));
    return make_float2(lo, hi);
}

__global__ __launch_bounds__(NT, 2)
void corr_kernel(const float* __restrict__ A,
                 const float* __restrict__ B,
                 float* __restrict__ out)
{
    __shared__ float As[3][ZC][TH][AROW];   // 3 * 4.5 KB
    __shared__ float Bs[3][ZC][BRN][BROW];  // 3 * 11 KB  (46.5 KB)

    const int tid = threadIdx.x;
    const int tx = tid & 3;          // w = w0 + 8*tx .. +7
    const int h  = (tid >> 2) & 7;
    const int j  = tid >> 5;         // warp index

    const int w0 = blockIdx.x * TW;
    const int h0 = blockIdx.y * TH;
    const int n  = blockIdx.z;

    const size_t plane = (size_t)H_ * W_;
    const float* Abase = A + (size_t)n * Z_ * plane;
    const float* Bbase = B + (size_t)n * Z_ * plane;

    // ------- fixed fill roles (computed once) -------
    unsigned boff[3], bsm[3];
    int bszv[3]; bool bact[3];
    #pragma unroll
    for (int s = 0; s < 3; s++) {
        int idx = tid + s * NT;
        bool act = idx < ZC * BRN * 10;
        int ii = act ? idx : 0;
        int z = ii / 160;
        int rem = ii - z * 160;
        int r = rem / 10;
        int c = rem - r * 10;
        int gh = h0 - 4 + r;
        int gw = w0 - 4 + 4 * c;
        bool v = ((unsigned)gh < H_) && ((unsigned)gw <= (W_ - 4));
        bact[s] = act;
        bszv[s] = v ? 16 : 0;
        boff[s] = v ? (unsigned)(z * plane + gh * W_ + gw) : 0u;
        bsm[s] = (unsigned)__cvta_generic_to_shared(&Bs[0][z][r][4 * c]);
    }
    const bool aact = tid < ZC * TH * 8;
    int ai = aact ? tid : 0;
    int az = ai >> 6;
    int ar = (ai >> 3) & 7;
    int ac = ai & 7;
    const unsigned aoff = (unsigned)(az * plane + (h0 + ar) * W_ + w0 + 4 * ac);
    const unsigned asm0 = (unsigned)__cvta_generic_to_shared(&As[0][az][ar][4 * ac]);

    const float* aRd0 = &As[0][0][h][8 * tx];
    const float* bRd0 = &Bs[0][0][h + j][8 * tx];

    // 36 packed accumulators: acc2[i][q] = {acc[i][2q], acc[i][2q+1]}
    u64 acc2[9][4];
    #pragma unroll
    for (int i = 0; i < 9; i++)
        #pragma unroll
        for (int q = 0; q < 4; q++)
            acc2[i][q] = 0ull;

    auto issue = [&](int chunk, int buf) {
        const float* bsrc = Bbase + (size_t)chunk * ZC * plane;
        const float* asrc = Abase + (size_t)chunk * ZC * plane;
        const unsigned bo = (unsigned)(buf * (BSZ * 4));
        const unsigned ao = (unsigned)(buf * (ASZ * 4));
        #pragma unroll
        for (int s = 0; s < 3; s++) {
            if (bact[s])
                asm volatile("cp.async.cg.shared.global [%0], [%1], 16, %2;"
                             :: "r"(bsm[s] + bo), "l"(bsrc + boff[s]), "r"(bszv[s]));
        }
        if (aact)
            asm volatile("cp.async.cg.shared.global [%0], [%1], 16, 16;"
                         :: "r"(asm0 + ao), "l"(asrc + aoff));
        asm volatile("cp.async.commit_group;");
    };

    issue(0, 0);
    issue(1, 1);

    int bufc = 0;
    for (int ch = 0; ch < NCH; ch++) {
        if (ch < NCH - 1) asm volatile("cp.async.wait_group 1;");
        else              asm volatile("cp.async.wait_group 0;");
        __syncthreads();

        int nb = bufc + 2; if (nb >= 3) nb -= 3;
        if (ch + 2 < NCH) issue(ch + 2, nb);

        const float* aRd = aRd0 + bufc * ASZ;
        const float* bRd = bRd0 + bufc * BSZ;

        #pragma unroll
        for (int z = 0; z < ZC; z++) {
            const float4 a0 = *(const float4*)(aRd + z * (TH * AROW));
            const float4 a1 = *(const float4*)(aRd + z * (TH * AROW) + 4);
            const float4 b0 = *(const float4*)(bRd + z * (BRN * BROW));
            const float4 b1 = *(const float4*)(bRd + z * (BRN * BROW) + 4);
            const float4 b2 = *(const float4*)(bRd + z * (BRN * BROW) + 8);
            const float4 b3 = *(const float4*)(bRd + z * (BRN * BROW) + 12);

            // a-pairs and even b-pairs alias float4 halves (packs coalesce)
            u64 ae[4] = {pk(a0.x, a0.y), pk(a0.z, a0.w),
                         pk(a1.x, a1.y), pk(a1.z, a1.w)};
            u64 be[8] = {pk(b0.x, b0.y), pk(b0.z, b0.w),
                         pk(b1.x, b1.y), pk(b1.z, b1.w),
                         pk(b2.x, b2.y), pk(b2.z, b2.w),
                         pk(b3.x, b3.y), pk(b3.z, b3.w)};
            const float bs[16] = {b0.x, b0.y, b0.z, b0.w, b1.x, b1.y, b1.z, b1.w,
                                  b2.x, b2.y, b2.z, b2.w, b3.x, b3.y, b3.z, b3.w};

            // even i: acc2[i][q] += ae[q] * be[q + i/2]
            #pragma unroll
            for (int i = 0; i < 9; i += 2)
                #pragma unroll
                for (int q = 0; q < 4; q++)
                    fma2(acc2[i][q], ae[q], be[q + i / 2]);

            // odd i: pack the odd-offset pair, consume immediately
            #pragma unroll
            for (int t = 0; t < 7; t++) {        // bo[t] = {bs[2t+1], bs[2t+2]}
                const u64 bo = pk(bs[2 * t + 1], bs[2 * t + 2]);
                #pragma unroll
                for (int i = 1; i < 9; i += 2) { // q = t - (i-1)/2
                    const int q = t - (i - 1) / 2;
                    if (q >= 0 && q < 4)
                        fma2(acc2[i][q], ae[q], bo);
                }
            }
        }

        bufc = (bufc == 2) ? 0 : bufc + 1;
    }

    // ------- store: 18 x STG.128 -------
    float* ob = out + (((size_t)n * 81 + j) * H_ + (h0 + h)) * W_ + w0 + 8 * tx;
    #pragma unroll
    for (int i = 0; i < 9; i++) {
        float2 p0 = unpk(acc2[i][0]);
        float2 p1 = unpk(acc2[i][1]);
        float2 p2 = unpk(acc2[i][2]);
        float2 p3 = unpk(acc2[i][3]);
        *(float4*)(ob + (size_t)(9 * i) * plane)     = make_float4(p0.x, p0.y, p1.x, p1.y);
        *(float4*)(ob + (size_t)(9 * i) * plane + 4) = make_float4(p2.x, p2.y, p3.x, p3.y);
    }
}

extern "C" void kernel_launch(void* const* d_in, const int* in_sizes, int n_in,
                              void* d_out, int out_size)
{
    const float* imgA = (const float*)d_in[0];
    const float* imgB = (const float*)d_in[1];
    float* out = (float*)d_out;

    dim3 grid(W_ / TW, H_ / TH, N_);
    corr_kernel<<<grid, NT>>>(imgA, imgB, out);
}